// round 15
// baseline (speedup 1.0000x reference)
#include <cuda_runtime.h>

// GaussianBlur v8: full-width tiles eliminate the x-halo redundancy.
// depthwise 21x21 Gaussian (sigma=5), reflect pad 10, [32,3,512,512] fp32.
// Tile 512x16 outputs, 544 threads, 3 CTA/SM (reg cap 40, smem 33.5KB):
//   phase 1: VERTICAL 21-tap from gmem. 536 column-tasks (12 reflected halo
//            cols + 512 + 12) -> ONE round over 544 threads (98.5% util).
//            28-reg sliding window, 2 stages x 8 outputs, refills
//            front-batched (MLP>=8). Dense coalesced loads. -> smem.
//   phase 2: HORIZONTAL 21-tap from smem: windows always aligned & in-tile
//            (halo cols pre-materialized) -> zero divergence. 7x LDS.128
//            conflict-free 4-output windows, FFMA-imm, STG.128 dense.
//            2048 tasks / 544 thr = 4 rounds (94% util).

#define W_ 512
#define H_ 512
#define NIMG 96
#define PAD 10

#define TY 16
#define HALO 12                      // >= PAD, multiple of 4 for alignment
#define VCOLS   (W_ + 2 * HALO)      // 536 phase-1 tasks
#define VSTRIDE VCOLS                // floats per smem row (2144B)
#define VWIN    (TY + 2 * PAD)       // 36 rows read per task
#define WNDW    28                   // phase-1 register window
#define NTHR    544

// 1D separable weights (validated rel_err 3.4e-7): exp(-(d^2)/50)/12.089199128
#define KW_INIT const float KW[21] = { \
    0.01119473f, 0.01636989f, 0.02299883f, 0.03104516f, 0.04026340f, \
    0.05017128f, 0.06006594f, 0.06909227f, 0.07635877f, 0.08108053f, \
    0.08271847f, \
    0.08108053f, 0.07635877f, 0.06909227f, 0.06006594f, 0.05017128f, \
    0.04026340f, 0.03104516f, 0.02299883f, 0.01636989f, 0.01119473f }

__device__ __forceinline__ int reflect512(int i) {
    // jnp.pad mode="reflect": -k -> k, 511+k -> 511-k (single reflection)
    i = (i < 0) ? -i : i;
    return (i > 511) ? (1022 - i) : i;
}

// ---- Phase-1 task: vertical conv of one column, 16 output rows ------------
// 28-slot window, slot(row) = row % 28 (compile-time after unroll).
// Stage 0: rows 0..27 -> outputs 0..7. Refill rows 28..35 (front-batched).
// Stage 1: outputs 8..15 from slots (rr+k)%28.
template <bool INTERIOR>
__device__ __forceinline__ void vtask(const float* __restrict__ img,
                                      float* __restrict__ dst,
                                      int yb, int gx) {
    KW_INIT;
    const float* __restrict__ p =
        img + (size_t)(INTERIOR ? yb : 0) * W_ + gx;

    float v[WNDW];
    #pragma unroll
    for (int j = 0; j < WNDW; ++j)
        v[j] = INTERIOR ? p[j * W_]
                        : img[(size_t)reflect512(yb + j) * W_ + gx];

    #pragma unroll
    for (int rr = 0; rr < 8; ++rr) {
        float a = 0.f;
        #pragma unroll
        for (int k = 0; k < 21; ++k)
            a = fmaf(KW[k], v[rr + k], a);
        dst[rr * VSTRIDE] = a;                  // conflict-free STS
    }
    #pragma unroll
    for (int j = WNDW; j < VWIN; ++j)           // rows 28..35
        v[j % WNDW] = INTERIOR ? p[j * W_]
                               : img[(size_t)reflect512(yb + j) * W_ + gx];
    #pragma unroll
    for (int rr = 8; rr < 16; ++rr) {
        float a = 0.f;
        #pragma unroll
        for (int k = 0; k < 21; ++k)
            a = fmaf(KW[k], v[(rr + k) % WNDW], a);
        dst[rr * VSTRIDE] = a;
    }
}

// Cold path (y-border tiles only): keep out of the hot instruction stream.
__device__ __noinline__ void vtask_border(const float* __restrict__ img,
                                          float* __restrict__ dst,
                                          int yb, int gx) {
    vtask<false>(img, dst, yb, gx);
}

__global__ __launch_bounds__(NTHR, 3)
void blur_v8(const float* __restrict__ in, float* __restrict__ out) {
    KW_INIT;
    __shared__ __align__(16) float Vs[TY * VSTRIDE];   // 34304 B

    const int n   = blockIdx.y;                // image
    const int y0  = blockIdx.x * TY;           // tile top row
    const int tid = threadIdx.x;

    const float* __restrict__ img = in + (size_t)n * (H_ * W_);

    // ---- Phase 1: vertical conv, gmem -> Vs. One task/thread, one round. --
    if (tid < VCOLS) {
        const int gx = reflect512(tid - HALO); // halo cols alias real cols
        const int yb = y0 - PAD;
        float* dst = Vs + tid;
        if (yb >= 0 && yb + VWIN <= H_)
            vtask<true>(img, dst, yb, gx);
        else
            vtask_border(img, dst, yb, gx);
    }
    __syncthreads();

    // ---- Phase 2: horizontal conv, Vs -> gmem. ----------------------------
    // Task t -> row r = t>>7, group g = t&127 (outputs 4g..4g+3 of row r).
    // Window = smem cols [4g .. 4g+27] (= global x [4g-12 .. 4g+15], covers
    // taps of outputs 4g..4g+3). Always in-bounds & 16B-aligned thanks to
    // the materialized halo columns. 7x LDS.128, 16B lane stride ->
    // conflict-free phases. STG.128 dense.
    float* __restrict__ outimg = out + (size_t)n * (H_ * W_);

    #pragma unroll
    for (int i = 0; i < 4; ++i) {
        const int t = i * NTHR + tid;
        if (t < TY * (W_ / 4)) {               // 2048 tasks
            const int r = t >> 7;
            const int g = t & 127;
            const float* __restrict__ src = Vs + r * VSTRIDE + 4 * g;

            float wv[28];
            #pragma unroll
            for (int j = 0; j < 7; ++j) {
                float4 q = *reinterpret_cast<const float4*>(src + 4 * j);
                wv[4 * j + 0] = q.x; wv[4 * j + 1] = q.y;
                wv[4 * j + 2] = q.z; wv[4 * j + 3] = q.w;
            }

            // output 4g+t0 uses taps at smem offsets (t0+2) .. (t0+22)
            float h0 = 0.f, h1 = 0.f, h2 = 0.f, h3 = 0.f;
            #pragma unroll
            for (int k = 0; k < 21; ++k) {
                const float w = KW[k];
                h0 = fmaf(w, wv[k + 2], h0);
                h1 = fmaf(w, wv[k + 3], h1);
                h2 = fmaf(w, wv[k + 4], h2);
                h3 = fmaf(w, wv[k + 5], h3);
            }
            *reinterpret_cast<float4*>(outimg + (size_t)(y0 + r) * W_ + 4 * g)
                = make_float4(h0, h1, h2, h3);
        }
    }
}

extern "C" void kernel_launch(void* const* d_in, const int* in_sizes, int n_in,
                              void* d_out, int out_size) {
    const float* x = (const float*)d_in[0];
    float* out = (float*)d_out;
    (void)in_sizes; (void)n_in; (void)out_size;

    // 32 y-tiles x 96 images = 3072 blocks of 544 threads
    blur_v8<<<dim3(H_ / TY, NIMG), NTHR>>>(x, out);
}